// round 13
// baseline (speedup 1.0000x reference)
#include <cuda_runtime.h>
#include <cuda_fp16.h>
#include <math.h>

#define MAXB 16384

// Scratch + accumulators (no allocations allowed; device globals).
__device__ float2 g_de[MAXB];                         // exact {d^2, e}
__device__ __align__(16) __half g_jd[MAXB];           // fp16 d^2
__device__ __align__(16) __half g_je[MAXB];           // fp16 -e
__device__ double g_sum;                              // sum of max(x,-1)
__device__ unsigned int g_tick;                       // completion counter

constexpr int TILE    = 256;   // i rows per block
constexpr int TJ      = 128;   // j rows per block (half tile -> 2x blocks)
constexpr int THREADS = 256;

// fp16x2 per-half sign flip: a ^ (b & 0x80008000)  (one LOP3)
__device__ __forceinline__ unsigned int sflip2(unsigned int a, unsigned int b) {
    unsigned int r;
    asm("lop3.b32 %0, %1, %2, %3, 0x78;"
        : "=r"(r) : "r"(a), "r"(b), "n"(0x80008000u));
    return r;
}
__device__ __forceinline__ __half2 u2h(unsigned int u) {
    __half2 h; *reinterpret_cast<unsigned int*>(&h) = u; return h;
}
__device__ __forceinline__ unsigned int h2u(__half2 h) {
    return *reinterpret_cast<unsigned int*>(&h);
}

// ---------------------------------------------------------------------------
// Kernel 1 (prep): one thread per row -> g_de (fp32) + g_jd/g_je (fp16).
// Pad rows: {+inf, 60000} -> every pad-involving slot nets 0 (see nslots).
// ---------------------------------------------------------------------------
__global__ __launch_bounds__(THREADS) void prep_kernel(
    const float* __restrict__ energies,
    const float* __restrict__ pv,
    const float* __restrict__ pt,
    int B, int P)
{
    int row = blockIdx.x * THREADS + threadIdx.x;
    float2 r;
    if (row < B) {
        float s = 0.0f;
        if (P == 16) {
            const float4* pv4 = (const float4*)(pv + (size_t)row * 16);
            const float4* pt4 = (const float4*)pt;
            #pragma unroll
            for (int q = 0; q < 4; q++) {
                float4 v = pv4[q];
                float4 w = pt4[q];
                float a = v.x - w.x, b = v.y - w.y;
                float c = v.z - w.z, d = v.w - w.w;
                s = fmaf(a, a, fmaf(b, b, fmaf(c, c, fmaf(d, d, s))));
            }
        } else {
            for (int q = 0; q < P; q++) {
                float df = pv[(size_t)row * P + q] - pt[q];
                s = fmaf(df, df, s);
            }
        }
        r = make_float2(s, energies[row]);
    } else {
        r = make_float2(INFINITY, 60000.0f);      // pad row
    }
    g_de[row] = r;
    g_jd[row] = __float2half_rn(r.x);
    g_je[row] = __float2half_rn(-r.y);
}

// ---------------------------------------------------------------------------
// Kernel 2 (pairs): 256(i) x 128(j) bricks, 2 j-halves per triangle pair
// -> NB = T*(T+1) blocks (~7 blocks/SM -> high occupancy; prologue is only
// two 256B coalesced loads so the R5 prologue-share trap doesn't apply).
//   * value per unordered pair: relu(x+1) = max(x,-1)+1,
//     x = sign(d2_j - d2_i) * (e_i - e_j)  (per-half sign-bit XOR).
//   * fp16x2 SIMD: 8 pairs / 22 instr, prefetched vectors, 4 acc chains,
//     fp32 spill every 8 iters. Diagonal bricks add a j>i lane mask
//     (indices offset by h*TJ) via __hgt2 + __hfma2.
//   * +1-per-slot total (exact, host-computed) added at the end.
//   * last-finishing block writes out[0] (self-resetting, graph-safe).
// ---------------------------------------------------------------------------
__global__ __launch_bounds__(THREADS) void pair_kernel(
    int T, int NB, double nslots, double invcnt,
    float* __restrict__ out)
{
    int t   = threadIdx.x;
    int bid = blockIdx.x;
    int p   = bid >> 1;        // triangle index
    int h   = bid & 1;         // j half

    // --- triangle decode: p -> (ti, tj), ti <= tj ---
    float tf = 2.0f * T + 1.0f;
    int ti = (int)floorf((tf - sqrtf(fmaxf(tf * tf - 8.0f * (float)p, 0.0f))) * 0.5f);
    if (ti < 0) ti = 0;
    if (ti > T - 1) ti = T - 1;
    while (ti > 0 && (ti * T - ti * (ti - 1) / 2) > p) ti--;
    while (((ti + 1) * T - (ti + 1) * ti / 2) <= p) ti++;
    int tj = ti + (p - (ti * T - ti * (ti - 1) / 2));
    bool diag = (ti == tj);

    __shared__ __half jd[TJ];
    __shared__ __half je[TJ];
    __shared__ float  ssum[THREADS / 32];

    // j half-tile: 256B each array (16 uint4), loaded by one warp
    int jbase = tj * TILE + h * TJ;
    if (t < 16) {
        ((uint4*)jd)[t] = ((const uint4*)(g_jd + jbase))[t];
    } else if (t < 32) {
        ((uint4*)je)[t - 16] = ((const uint4*)(g_je + jbase))[t - 16];
    }
    float2 mi = g_de[ti * TILE + t];          // my i row (exact fp32)
    __syncthreads();

    unsigned int ndi2 = h2u(__float2half2_rn(-mi.x));   // (-d2_i, -d2_i)
    unsigned int ei2  = h2u(__float2half2_rn(mi.y));    // ( e_i ,  e_i )
    const __half2 neg1 = __floats2half2_rn(-1.0f, -1.0f);

    const uint4* jd4 = (const uint4*)jd;   // 8 halves per uint4
    const uint4* je4 = (const uint4*)je;

    float facc = 0.0f;

    if (!diag) {
        // ---- off-diagonal: 8 pairs / iter, 16 iters ----
        uint4 qd = jd4[0], qe = je4[0];
        #pragma unroll
        for (int kk = 0; kk < 2; kk++) {                 // fp32 spill chunks
            __half2 a0 = u2h(0u), a1 = u2h(0u), a2 = u2h(0u), a3 = u2h(0u);
            #pragma unroll
            for (int u = 0; u < 8; u++) {
                int idx = kk * 8 + u;
                uint4 nd, ne;
                if (idx < 15) { nd = jd4[idx + 1]; ne = je4[idx + 1]; }
                unsigned int dd0 = h2u(__hadd2(u2h(qd.x), u2h(ndi2)));
                unsigned int dd1 = h2u(__hadd2(u2h(qd.y), u2h(ndi2)));
                unsigned int dd2 = h2u(__hadd2(u2h(qd.z), u2h(ndi2)));
                unsigned int dd3 = h2u(__hadd2(u2h(qd.w), u2h(ndi2)));
                unsigned int de0 = h2u(__hadd2(u2h(ei2), u2h(qe.x)));
                unsigned int de1 = h2u(__hadd2(u2h(ei2), u2h(qe.y)));
                unsigned int de2 = h2u(__hadd2(u2h(ei2), u2h(qe.z)));
                unsigned int de3 = h2u(__hadd2(u2h(ei2), u2h(qe.w)));
                a0 = __hadd2(a0, __hmax2(u2h(sflip2(de0, dd0)), neg1));
                a1 = __hadd2(a1, __hmax2(u2h(sflip2(de1, dd1)), neg1));
                a2 = __hadd2(a2, __hmax2(u2h(sflip2(de2, dd2)), neg1));
                a3 = __hadd2(a3, __hmax2(u2h(sflip2(de3, dd3)), neg1));
                qd = nd; qe = ne;
            }
            float2 f0 = __half22float2(a0), f1 = __half22float2(a1);
            float2 f2 = __half22float2(a2), f3 = __half22float2(a3);
            facc += ((f0.x + f0.y) + (f1.x + f1.y))
                  + ((f2.x + f2.y) + (f3.x + f3.y));
        }
    } else {
        // ---- diagonal: j>i lane mask via fp16 index compare ----
        const __half2 tt    = __float2half2_rn((float)t);
        const __half2 eight = __float2half2_rn(8.0f);
        float jb = (float)(h * TJ);
        __half2 jv0 = __floats2half2_rn(jb + 0.0f, jb + 1.0f);
        __half2 jv1 = __floats2half2_rn(jb + 2.0f, jb + 3.0f);
        __half2 jv2 = __floats2half2_rn(jb + 4.0f, jb + 5.0f);
        __half2 jv3 = __floats2half2_rn(jb + 6.0f, jb + 7.0f);
        #pragma unroll
        for (int kk = 0; kk < 2; kk++) {
            __half2 a0 = u2h(0u), a1 = u2h(0u), a2 = u2h(0u), a3 = u2h(0u);
            #pragma unroll
            for (int u = 0; u < 8; u++) {
                int idx = kk * 8 + u;
                uint4 qd = jd4[idx], qe = je4[idx];
                unsigned int dd0 = h2u(__hadd2(u2h(qd.x), u2h(ndi2)));
                unsigned int dd1 = h2u(__hadd2(u2h(qd.y), u2h(ndi2)));
                unsigned int dd2 = h2u(__hadd2(u2h(qd.z), u2h(ndi2)));
                unsigned int dd3 = h2u(__hadd2(u2h(qd.w), u2h(ndi2)));
                unsigned int de0 = h2u(__hadd2(u2h(ei2), u2h(qe.x)));
                unsigned int de1 = h2u(__hadd2(u2h(ei2), u2h(qe.y)));
                unsigned int de2 = h2u(__hadd2(u2h(ei2), u2h(qe.z)));
                unsigned int de3 = h2u(__hadd2(u2h(ei2), u2h(qe.w)));
                __half2 c0 = __hmax2(u2h(sflip2(de0, dd0)), neg1);
                __half2 c1 = __hmax2(u2h(sflip2(de1, dd1)), neg1);
                __half2 c2 = __hmax2(u2h(sflip2(de2, dd2)), neg1);
                __half2 c3 = __hmax2(u2h(sflip2(de3, dd3)), neg1);
                a0 = __hfma2(__hgt2(jv0, tt), c0, a0);
                a1 = __hfma2(__hgt2(jv1, tt), c1, a1);
                a2 = __hfma2(__hgt2(jv2, tt), c2, a2);
                a3 = __hfma2(__hgt2(jv3, tt), c3, a3);
                jv0 = __hadd2(jv0, eight);
                jv1 = __hadd2(jv1, eight);
                jv2 = __hadd2(jv2, eight);
                jv3 = __hadd2(jv3, eight);
            }
            float2 f0 = __half22float2(a0), f1 = __half22float2(a1);
            float2 f2 = __half22float2(a2), f3 = __half22float2(a3);
            facc += ((f0.x + f0.y) + (f1.x + f1.y))
                  + ((f2.x + f2.y) + (f3.x + f3.y));
        }
    }

    // --- block reduction ---
    #pragma unroll
    for (int o = 16; o > 0; o >>= 1)
        facc += __shfl_down_sync(0xFFFFFFFFu, facc, o);

    int w = t >> 5, l = t & 31;
    if (l == 0) ssum[w] = facc;
    __syncthreads();

    // --- global accumulation + last-block epilogue ---
    if (t == 0) {
        float a = 0.0f;
        #pragma unroll
        for (int k = 0; k < THREADS / 32; k++) a += ssum[k];
        atomicAdd(&g_sum, (double)a);
        __threadfence();
        unsigned int old = atomicInc(&g_tick, (unsigned int)(NB - 1));
        if (old == (unsigned int)(NB - 1)) {
            unsigned long long bits =
                atomicExch((unsigned long long*)&g_sum, 0ull); // read + reset
            out[0] = (float)((__longlong_as_double(bits) + nslots) * invcnt);
        }
    }
}

// ---------------------------------------------------------------------------
extern "C" void kernel_launch(void* const* d_in, const int* in_sizes, int n_in,
                              void* d_out, int out_size) {
    const float* energies = (const float*)d_in[0];   // (B, 1)
    const float* pv       = (const float*)d_in[1];   // (B, P)
    const float* pt       = (const float*)d_in[2];   // (P,)
    float* out            = (float*)d_out;

    int B = in_sizes[0];
    int P = in_sizes[2];
    if (B > MAXB) B = MAXB;

    int T  = (B + TILE - 1) / TILE;
    int NB = T * (T + 1);               // two j-halves per triangle pair

    prep_kernel<<<T, THREADS>>>(energies, pv, pt, B, P);

    // exact +1-per-slot total; pad rows net 0 except pad-pad slots in the
    // final diagonal brick (value 0 but +1 counted) -> subtract them.
    double npad = (double)(T * TILE - B);
    double nslots = (double)(T * (T - 1) / 2) * (double)TILE * (double)TILE
                  + (double)T * (double)(TILE * (TILE - 1) / 2)
                  - npad * (npad - 1.0) * 0.5;

    double cnt = (double)B * (double)(B - 1) * 0.5;
    if (cnt < 1.0) cnt = 1.0;

    pair_kernel<<<NB, THREADS>>>(T, NB, nslots, 1.0 / cnt, out);
}

// round 14
// speedup vs baseline: 1.0655x; 1.0655x over previous
#include <cuda_runtime.h>
#include <cuda_fp16.h>
#include <math.h>

#define MAXB 16384

// Scratch + accumulators (no allocations allowed; device globals).
__device__ float2 g_de[MAXB];                         // exact {d^2, e}
__device__ __align__(16) __half g_jd[MAXB];           // fp16 d^2
__device__ __align__(16) __half g_je[MAXB];           // fp16 -e
__device__ double g_sum[8];                           // spread partial sums
__device__ unsigned int g_tick;                       // completion counter

constexpr int TILE    = 256;
constexpr int THREADS = 256;

// fp16x2 per-half sign flip: a ^ (b & 0x80008000)  (one LOP3)
__device__ __forceinline__ unsigned int sflip2(unsigned int a, unsigned int b) {
    unsigned int r;
    asm("lop3.b32 %0, %1, %2, %3, 0x78;"
        : "=r"(r) : "r"(a), "r"(b), "n"(0x80008000u));
    return r;
}
__device__ __forceinline__ __half2 u2h(unsigned int u) {
    __half2 h; *reinterpret_cast<unsigned int*>(&h) = u; return h;
}
__device__ __forceinline__ unsigned int h2u(__half2 h) {
    return *reinterpret_cast<unsigned int*>(&h);
}

// ---------------------------------------------------------------------------
// Kernel 1 (prep): one thread per row -> g_de (fp32) + g_jd/g_je (fp16).
// Pad rows: {+inf, 60000} -> every pad-involving slot nets 0 (see nslots).
// ---------------------------------------------------------------------------
__global__ __launch_bounds__(THREADS) void prep_kernel(
    const float* __restrict__ energies,
    const float* __restrict__ pv,
    const float* __restrict__ pt,
    int B, int P)
{
    int row = blockIdx.x * THREADS + threadIdx.x;
    float2 r;
    if (row < B) {
        float s = 0.0f;
        if (P == 16) {
            const float4* pv4 = (const float4*)(pv + (size_t)row * 16);
            const float4* pt4 = (const float4*)pt;
            #pragma unroll
            for (int q = 0; q < 4; q++) {
                float4 v = pv4[q];
                float4 w = pt4[q];
                float a = v.x - w.x, b = v.y - w.y;
                float c = v.z - w.z, d = v.w - w.w;
                s = fmaf(a, a, fmaf(b, b, fmaf(c, c, fmaf(d, d, s))));
            }
        } else {
            for (int q = 0; q < P; q++) {
                float df = pv[(size_t)row * P + q] - pt[q];
                s = fmaf(df, df, s);
            }
        }
        r = make_float2(s, energies[row]);
    } else {
        r = make_float2(INFINITY, 60000.0f);      // pad row
    }
    g_de[row] = r;
    g_jd[row] = __float2half_rn(r.x);
    g_je[row] = __float2half_rn(-r.y);
}

// ---------------------------------------------------------------------------
// Kernel 2 (pairs): triangle-tiled 256x256 bricks (T*(T+1)/2 blocks).
// Launched with PDL: decode overlaps prep; cudaGridDependencySynchronize()
// guards the first read of prep outputs.
//   * value per unordered pair: relu(x+1) = max(x,-1)+1,
//     x = sign(d2_j - d2_i) * (e_i - e_j)  (per-half sign-bit XOR).
//   * fp16x2 SIMD: 8 pairs / ~22 instr, prefetched vectors, 4 acc chains,
//     fp32 spill every 16 iters; diagonal bricks add j>i lane mask.
//   * partial sums spread over 8 double slots (no same-address burst);
//     last-finishing block (g_tick) gathers, adds nslots, writes out[0],
//     resetting everything for graph replay.
// ---------------------------------------------------------------------------
__global__ __launch_bounds__(THREADS) void pair_kernel(
    int T, int NB, double nslots, double invcnt,
    float* __restrict__ out)
{
    int t   = threadIdx.x;
    int bid = blockIdx.x;

    // --- triangle decode first (independent of prep outputs) ---
    float tf = 2.0f * T + 1.0f;
    int ti = (int)floorf((tf - sqrtf(fmaxf(tf * tf - 8.0f * (float)bid, 0.0f))) * 0.5f);
    if (ti < 0) ti = 0;
    if (ti > T - 1) ti = T - 1;
    while (ti > 0 && (ti * T - ti * (ti - 1) / 2) > bid) ti--;
    while (((ti + 1) * T - (ti + 1) * ti / 2) <= bid) ti++;
    int tj = ti + (bid - (ti * T - ti * (ti - 1) / 2));
    bool diag = (ti == tj);

    // --- PDL: wait until prep's memory is visible ---
    cudaGridDependencySynchronize();

    __shared__ __half jd[TILE];
    __shared__ __half je[TILE];
    __shared__ float  ssum[THREADS / 32];

    // j tile: 512B each array, loaded by 64 threads as uint4
    if (t < 32) {
        ((uint4*)jd)[t] = ((const uint4*)(g_jd + tj * TILE))[t];
    } else if (t < 64) {
        ((uint4*)je)[t - 32] = ((const uint4*)(g_je + tj * TILE))[t - 32];
    }
    float2 mi = g_de[ti * TILE + t];          // my i row (exact fp32)
    __syncthreads();

    unsigned int ndi2 = h2u(__float2half2_rn(-mi.x));   // (-d2_i, -d2_i)
    unsigned int ei2  = h2u(__float2half2_rn(mi.y));    // ( e_i ,  e_i )
    const __half2 neg1 = __floats2half2_rn(-1.0f, -1.0f);

    const uint4* jd4 = (const uint4*)jd;   // 8 halves per uint4
    const uint4* je4 = (const uint4*)je;

    float facc = 0.0f;

    if (!diag) {
        // ---- off-diagonal: 8 pairs / iter, 32 iters ----
        uint4 qd = jd4[0], qe = je4[0];
        #pragma unroll
        for (int kk = 0; kk < 2; kk++) {                 // fp32 spill chunks
            __half2 a0 = u2h(0u), a1 = u2h(0u), a2 = u2h(0u), a3 = u2h(0u);
            #pragma unroll
            for (int u = 0; u < 16; u++) {
                int idx = kk * 16 + u;
                uint4 nd, ne;
                if (idx < 31) { nd = jd4[idx + 1]; ne = je4[idx + 1]; }
                unsigned int dd0 = h2u(__hadd2(u2h(qd.x), u2h(ndi2)));
                unsigned int dd1 = h2u(__hadd2(u2h(qd.y), u2h(ndi2)));
                unsigned int dd2 = h2u(__hadd2(u2h(qd.z), u2h(ndi2)));
                unsigned int dd3 = h2u(__hadd2(u2h(qd.w), u2h(ndi2)));
                unsigned int de0 = h2u(__hadd2(u2h(ei2), u2h(qe.x)));
                unsigned int de1 = h2u(__hadd2(u2h(ei2), u2h(qe.y)));
                unsigned int de2 = h2u(__hadd2(u2h(ei2), u2h(qe.z)));
                unsigned int de3 = h2u(__hadd2(u2h(ei2), u2h(qe.w)));
                a0 = __hadd2(a0, __hmax2(u2h(sflip2(de0, dd0)), neg1));
                a1 = __hadd2(a1, __hmax2(u2h(sflip2(de1, dd1)), neg1));
                a2 = __hadd2(a2, __hmax2(u2h(sflip2(de2, dd2)), neg1));
                a3 = __hadd2(a3, __hmax2(u2h(sflip2(de3, dd3)), neg1));
                qd = nd; qe = ne;
            }
            float2 f0 = __half22float2(a0), f1 = __half22float2(a1);
            float2 f2 = __half22float2(a2), f3 = __half22float2(a3);
            facc += ((f0.x + f0.y) + (f1.x + f1.y))
                  + ((f2.x + f2.y) + (f3.x + f3.y));
        }
    } else {
        // ---- diagonal: j>i lane mask via fp16 index compare ----
        const __half2 tt    = __float2half2_rn((float)t);
        const __half2 eight = __float2half2_rn(8.0f);
        __half2 jv0 = __floats2half2_rn(0.0f, 1.0f);
        __half2 jv1 = __floats2half2_rn(2.0f, 3.0f);
        __half2 jv2 = __floats2half2_rn(4.0f, 5.0f);
        __half2 jv3 = __floats2half2_rn(6.0f, 7.0f);
        #pragma unroll
        for (int kk = 0; kk < 2; kk++) {
            __half2 a0 = u2h(0u), a1 = u2h(0u), a2 = u2h(0u), a3 = u2h(0u);
            #pragma unroll
            for (int u = 0; u < 16; u++) {
                int idx = kk * 16 + u;
                uint4 qd = jd4[idx], qe = je4[idx];
                unsigned int dd0 = h2u(__hadd2(u2h(qd.x), u2h(ndi2)));
                unsigned int dd1 = h2u(__hadd2(u2h(qd.y), u2h(ndi2)));
                unsigned int dd2 = h2u(__hadd2(u2h(qd.z), u2h(ndi2)));
                unsigned int dd3 = h2u(__hadd2(u2h(qd.w), u2h(ndi2)));
                unsigned int de0 = h2u(__hadd2(u2h(ei2), u2h(qe.x)));
                unsigned int de1 = h2u(__hadd2(u2h(ei2), u2h(qe.y)));
                unsigned int de2 = h2u(__hadd2(u2h(ei2), u2h(qe.z)));
                unsigned int de3 = h2u(__hadd2(u2h(ei2), u2h(qe.w)));
                __half2 c0 = __hmax2(u2h(sflip2(de0, dd0)), neg1);
                __half2 c1 = __hmax2(u2h(sflip2(de1, dd1)), neg1);
                __half2 c2 = __hmax2(u2h(sflip2(de2, dd2)), neg1);
                __half2 c3 = __hmax2(u2h(sflip2(de3, dd3)), neg1);
                a0 = __hfma2(__hgt2(jv0, tt), c0, a0);
                a1 = __hfma2(__hgt2(jv1, tt), c1, a1);
                a2 = __hfma2(__hgt2(jv2, tt), c2, a2);
                a3 = __hfma2(__hgt2(jv3, tt), c3, a3);
                jv0 = __hadd2(jv0, eight);
                jv1 = __hadd2(jv1, eight);
                jv2 = __hadd2(jv2, eight);
                jv3 = __hadd2(jv3, eight);
            }
            float2 f0 = __half22float2(a0), f1 = __half22float2(a1);
            float2 f2 = __half22float2(a2), f3 = __half22float2(a3);
            facc += ((f0.x + f0.y) + (f1.x + f1.y))
                  + ((f2.x + f2.y) + (f3.x + f3.y));
        }
    }

    // --- block reduction ---
    #pragma unroll
    for (int o = 16; o > 0; o >>= 1)
        facc += __shfl_down_sync(0xFFFFFFFFu, facc, o);

    int w = t >> 5, l = t & 31;
    if (l == 0) ssum[w] = facc;
    __syncthreads();

    // --- spread global accumulation + last-block epilogue ---
    if (t == 0) {
        float a = 0.0f;
        #pragma unroll
        for (int k = 0; k < THREADS / 32; k++) a += ssum[k];
        atomicAdd(&g_sum[bid & 7], (double)a);     // 8 slots -> no burst
        __threadfence();
        unsigned int old = atomicInc(&g_tick, (unsigned int)(NB - 1));
        if (old == (unsigned int)(NB - 1)) {
            __threadfence();
            double tot = 0.0;
            #pragma unroll
            for (int k = 0; k < 8; k++) {
                unsigned long long b =
                    atomicExch((unsigned long long*)&g_sum[k], 0ull);
                tot += __longlong_as_double(b);    // read + reset (replayable)
            }
            out[0] = (float)((tot + nslots) * invcnt);
        }
    }
}

// ---------------------------------------------------------------------------
extern "C" void kernel_launch(void* const* d_in, const int* in_sizes, int n_in,
                              void* d_out, int out_size) {
    const float* energies = (const float*)d_in[0];   // (B, 1)
    const float* pv       = (const float*)d_in[1];   // (B, P)
    const float* pt       = (const float*)d_in[2];   // (P,)
    float* out            = (float*)d_out;

    int B = in_sizes[0];
    int P = in_sizes[2];
    if (B > MAXB) B = MAXB;

    int T  = (B + TILE - 1) / TILE;
    int NB = T * (T + 1) / 2;

    prep_kernel<<<T, THREADS>>>(energies, pv, pt, B, P);

    // exact +1-per-slot total; pad rows net 0 except pad-pad slots in the
    // final diagonal brick (value 0 but +1 counted) -> subtract them.
    double npad = (double)(T * TILE - B);
    double nslots = (double)(T * (T - 1) / 2) * (double)TILE * (double)TILE
                  + (double)T * (double)(TILE * (TILE - 1) / 2)
                  - npad * (npad - 1.0) * 0.5;

    double cnt = (double)B * (double)(B - 1) * 0.5;
    if (cnt < 1.0) cnt = 1.0;
    double invcnt = 1.0 / cnt;

    // PDL launch: pair kernel's launch+decode overlaps prep's execution.
    cudaLaunchConfig_t cfg = {};
    cfg.gridDim  = dim3((unsigned)NB, 1, 1);
    cfg.blockDim = dim3((unsigned)THREADS, 1, 1);
    cfg.dynamicSmemBytes = 0;
    cfg.stream = 0;
    cudaLaunchAttribute attrs[1];
    attrs[0].id = cudaLaunchAttributeProgrammaticStreamSerialization;
    attrs[0].val.programmaticStreamSerializationAllowed = 1;
    cfg.attrs = attrs;
    cfg.numAttrs = 1;
    cudaError_t err = cudaLaunchKernelEx(&cfg, pair_kernel,
                                         T, NB, nslots, invcnt, out);
    if (err != cudaSuccess) {
        // fallback: plain serialized launch
        pair_kernel<<<NB, THREADS>>>(T, NB, nslots, invcnt, out);
    }
}

// round 15
// speedup vs baseline: 1.1830x; 1.1103x over previous
#include <cuda_runtime.h>
#include <cuda_fp16.h>
#include <math.h>

#define MAXB 16384

// Scratch + accumulators (no allocations allowed; device globals).
__device__ float2 g_de[MAXB];                         // exact {d^2, e}
__device__ __align__(16) __half g_jd[MAXB];           // fp16 d^2
__device__ __align__(16) __half g_je[MAXB];           // fp16 -e
__device__ double g_sum[8];                           // spread partial sums
__device__ unsigned int g_tick;                       // completion counter

constexpr int TILE     = 512;   // brick edge (i rows = threads)
constexpr int THREADS  = 512;
constexpr int PTHREADS = 256;   // prep block size

// fp16x2 per-half sign flip: a ^ (b & 0x80008000)  (one LOP3)
__device__ __forceinline__ unsigned int sflip2(unsigned int a, unsigned int b) {
    unsigned int r;
    asm("lop3.b32 %0, %1, %2, %3, 0x78;"
        : "=r"(r) : "r"(a), "r"(b), "n"(0x80008000u));
    return r;
}
__device__ __forceinline__ __half2 u2h(unsigned int u) {
    __half2 h; *reinterpret_cast<unsigned int*>(&h) = u; return h;
}
__device__ __forceinline__ unsigned int h2u(__half2 h) {
    return *reinterpret_cast<unsigned int*>(&h);
}

// ---------------------------------------------------------------------------
// Kernel 1 (prep): one thread per row -> g_de (fp32) + g_jd/g_je (fp16).
// Pad rows: {+inf, 60000} -> every pad-involving slot nets 0 (see nslots).
// ---------------------------------------------------------------------------
__global__ __launch_bounds__(PTHREADS) void prep_kernel(
    const float* __restrict__ energies,
    const float* __restrict__ pv,
    const float* __restrict__ pt,
    int B, int P)
{
    int row = blockIdx.x * PTHREADS + threadIdx.x;
    float2 r;
    if (row < B) {
        float s = 0.0f;
        if (P == 16) {
            const float4* pv4 = (const float4*)(pv + (size_t)row * 16);
            const float4* pt4 = (const float4*)pt;
            #pragma unroll
            for (int q = 0; q < 4; q++) {
                float4 v = pv4[q];
                float4 w = pt4[q];
                float a = v.x - w.x, b = v.y - w.y;
                float c = v.z - w.z, d = v.w - w.w;
                s = fmaf(a, a, fmaf(b, b, fmaf(c, c, fmaf(d, d, s))));
            }
        } else {
            for (int q = 0; q < P; q++) {
                float df = pv[(size_t)row * P + q] - pt[q];
                s = fmaf(df, df, s);
            }
        }
        r = make_float2(s, energies[row]);
    } else {
        r = make_float2(INFINITY, 60000.0f);      // pad row
    }
    g_de[row] = r;
    g_jd[row] = __float2half_rn(r.x);
    g_je[row] = __float2half_rn(-r.y);
}

// ---------------------------------------------------------------------------
// Kernel 2 (pairs): 512x512 bricks, T*(T+1)/2 = 136 blocks = ONE wave.
//   * value per unordered pair: relu(x+1) = max(x,-1)+1,
//     x = sign(d2_j - d2_i) * (e_i - e_j)  (per-half sign-bit XOR).
//   * SINGLE code path: diagonal bricks run the same unmasked loop over all
//     ordered (i,j) -- each unordered pair is counted twice, self-pairs
//     contribute exactly 0 (dd=0 -> x=0 -> max(0,-1)=0) -- then facc *= 0.5.
//   * fp16x2 SIMD: 8 pairs / ~22 instr, prefetched vectors, 4 acc chains,
//     fp32 spill every 16 iters (validated cadence, rel_err ~2.6e-6).
//   * partial sums spread over 8 double slots; last-finishing block (g_tick)
//     gathers, adds nslots, writes out[0]; all counters self-reset.
// ---------------------------------------------------------------------------
__global__ __launch_bounds__(THREADS) void pair_kernel(
    int T, int NB, double nslots, double invcnt,
    float* __restrict__ out)
{
    int t   = threadIdx.x;
    int bid = blockIdx.x;

    // --- triangle decode: bid -> (ti, tj), ti <= tj ---
    float tf = 2.0f * T + 1.0f;
    int ti = (int)floorf((tf - sqrtf(fmaxf(tf * tf - 8.0f * (float)bid, 0.0f))) * 0.5f);
    if (ti < 0) ti = 0;
    if (ti > T - 1) ti = T - 1;
    while (ti > 0 && (ti * T - ti * (ti - 1) / 2) > bid) ti--;
    while (((ti + 1) * T - (ti + 1) * ti / 2) <= bid) ti++;
    int tj = ti + (bid - (ti * T - ti * (ti - 1) / 2));
    bool diag = (ti == tj);

    __shared__ __half jd[TILE];          // 1 KB
    __shared__ __half je[TILE];          // 1 KB
    __shared__ float  ssum[THREADS / 32];

    // j tile: 1KB each array (64 uint4), loaded by 128 threads
    if (t < 64) {
        ((uint4*)jd)[t] = ((const uint4*)(g_jd + tj * TILE))[t];
    } else if (t < 128) {
        ((uint4*)je)[t - 64] = ((const uint4*)(g_je + tj * TILE))[t - 64];
    }
    float2 mi = g_de[ti * TILE + t];          // my i row (exact fp32)
    __syncthreads();

    unsigned int ndi2 = h2u(__float2half2_rn(-mi.x));   // (-d2_i, -d2_i)
    unsigned int ei2  = h2u(__float2half2_rn(mi.y));    // ( e_i ,  e_i )
    const __half2 neg1 = __floats2half2_rn(-1.0f, -1.0f);

    const uint4* jd4 = (const uint4*)jd;   // 8 halves per uint4
    const uint4* je4 = (const uint4*)je;

    float facc = 0.0f;

    // ---- unmasked loop: 8 pairs / iter, 64 iters, 4 spill chunks ----
    uint4 qd = jd4[0], qe = je4[0];
    #pragma unroll
    for (int kk = 0; kk < 4; kk++) {                 // fp32 spill chunks
        __half2 a0 = u2h(0u), a1 = u2h(0u), a2 = u2h(0u), a3 = u2h(0u);
        #pragma unroll
        for (int u = 0; u < 16; u++) {
            int idx = kk * 16 + u;
            uint4 nd, ne;
            if (idx < 63) { nd = jd4[idx + 1]; ne = je4[idx + 1]; }
            unsigned int dd0 = h2u(__hadd2(u2h(qd.x), u2h(ndi2)));
            unsigned int dd1 = h2u(__hadd2(u2h(qd.y), u2h(ndi2)));
            unsigned int dd2 = h2u(__hadd2(u2h(qd.z), u2h(ndi2)));
            unsigned int dd3 = h2u(__hadd2(u2h(qd.w), u2h(ndi2)));
            unsigned int de0 = h2u(__hadd2(u2h(ei2), u2h(qe.x)));
            unsigned int de1 = h2u(__hadd2(u2h(ei2), u2h(qe.y)));
            unsigned int de2 = h2u(__hadd2(u2h(ei2), u2h(qe.z)));
            unsigned int de3 = h2u(__hadd2(u2h(ei2), u2h(qe.w)));
            a0 = __hadd2(a0, __hmax2(u2h(sflip2(de0, dd0)), neg1));
            a1 = __hadd2(a1, __hmax2(u2h(sflip2(de1, dd1)), neg1));
            a2 = __hadd2(a2, __hmax2(u2h(sflip2(de2, dd2)), neg1));
            a3 = __hadd2(a3, __hmax2(u2h(sflip2(de3, dd3)), neg1));
            qd = nd; qe = ne;
        }
        float2 f0 = __half22float2(a0), f1 = __half22float2(a1);
        float2 f2 = __half22float2(a2), f3 = __half22float2(a3);
        facc += ((f0.x + f0.y) + (f1.x + f1.y))
              + ((f2.x + f2.y) + (f3.x + f3.y));
    }

    // diagonal brick counted every unordered pair twice (self-pairs = 0)
    if (diag) facc *= 0.5f;

    // --- block reduction ---
    #pragma unroll
    for (int o = 16; o > 0; o >>= 1)
        facc += __shfl_down_sync(0xFFFFFFFFu, facc, o);

    int w = t >> 5, l = t & 31;
    if (l == 0) ssum[w] = facc;
    __syncthreads();

    // --- spread global accumulation + last-block epilogue ---
    if (t == 0) {
        float a = 0.0f;
        #pragma unroll
        for (int k = 0; k < THREADS / 32; k++) a += ssum[k];
        atomicAdd(&g_sum[bid & 7], (double)a);     // 8 slots -> no burst
        __threadfence();
        unsigned int old = atomicInc(&g_tick, (unsigned int)(NB - 1));
        if (old == (unsigned int)(NB - 1)) {
            __threadfence();
            double tot = 0.0;
            #pragma unroll
            for (int k = 0; k < 8; k++) {
                unsigned long long b =
                    atomicExch((unsigned long long*)&g_sum[k], 0ull);
                tot += __longlong_as_double(b);    // read + reset (replayable)
            }
            out[0] = (float)((tot + nslots) * invcnt);
        }
    }
}

// ---------------------------------------------------------------------------
extern "C" void kernel_launch(void* const* d_in, const int* in_sizes, int n_in,
                              void* d_out, int out_size) {
    const float* energies = (const float*)d_in[0];   // (B, 1)
    const float* pv       = (const float*)d_in[1];   // (B, P)
    const float* pt       = (const float*)d_in[2];   // (P,)
    float* out            = (float*)d_out;

    int B = in_sizes[0];
    int P = in_sizes[2];
    if (B > MAXB) B = MAXB;

    int T  = (B + TILE - 1) / TILE;
    int NB = T * (T + 1) / 2;

    int prows = T * TILE;
    prep_kernel<<<prows / PTHREADS, PTHREADS>>>(energies, pv, pt, B, P);

    // exact +1-per-slot total (unordered slots):
    //   off-diag bricks: TILE*TILE each; diag bricks: TILE*(TILE-1)/2 each;
    //   pad rows net 0 except pad-pad slots (value 0 but +1) -> subtract.
    double npad = (double)(T * TILE - B);
    double nslots = (double)(T * (T - 1) / 2) * (double)TILE * (double)TILE
                  + (double)T * (double)((long long)TILE * (TILE - 1) / 2)
                  - npad * (npad - 1.0) * 0.5;

    double cnt = (double)B * (double)(B - 1) * 0.5;
    if (cnt < 1.0) cnt = 1.0;

    pair_kernel<<<NB, THREADS>>>(T, NB, nslots, 1.0 / cnt, out);
}